// round 7
// baseline (speedup 1.0000x reference)
#include <cuda_runtime.h>

#define B_ 4
#define F_ 1025
#define C_ 6
#define T_ 1000
#define NPAIR 21
#define NOFF 15
#define THREADS 128

#define DIAG_EPS 1e-7f
#define EPS_ 1e-8f
#define PSD_EPS 1e-15f
#define ACC_N 74

__device__ __forceinline__ float2 cdiv(float2 a, float2 b) {
    float inv = 1.0f / (b.x*b.x + b.y*b.y);
    return make_float2((a.x*b.x + a.y*b.y)*inv, (a.y*b.x - a.x*b.y)*inv);
}

__device__ __forceinline__ long long cmin(long long a, long long b) { return a < b ? a : b; }

// out_mode: 0 = interleaved float2 (out_size >= 2*B*F*T), 1 = real part only.
__global__ __launch_bounds__(THREADS)
void mvdr_kernel(const float* __restrict__ spec_r, long long sr_n,
                 const float* __restrict__ spec_i, long long si_n,
                 const float* __restrict__ mask_s, long long ms_n,
                 const float* __restrict__ mask_n, long long mn_n,
                 float* __restrict__ out, long long out_n, int out_mode)
{
    __shared__ float2 Xsh[C_][T_];
    __shared__ float  s_acc[ACC_N];
    __shared__ float2 M[C_][2*C_];
    __shared__ float2 fac[C_];
    __shared__ float2 wc[C_];

    const int bf  = blockIdx.x;
    const int tid = threadIdx.x;

    if (tid < ACC_N) s_acc[tid] = 0.0f;
    __syncthreads();

    // ---------------- Phase 1: stream X once, accumulate both PSDs ----------------
    float asr[NPAIR], anr[NPAIR], asi[NOFF], ani[NOFF];
    #pragma unroll
    for (int k = 0; k < NPAIR; ++k) { asr[k] = 0.f; anr[k] = 0.f; }
    #pragma unroll
    for (int k = 0; k < NOFF; ++k)  { asi[k] = 0.f; ani[k] = 0.f; }
    float sms = 0.f, smn = 0.f;

    const long long specBase = (long long)bf * (C_*T_);
    const long long maskBase = (long long)bf * T_;

    for (int t = tid; t < T_; t += THREADS) {
        float xr[C_], xi[C_];
        #pragma unroll
        for (int c = 0; c < C_; ++c) {
            xr[c] = spec_r[cmin(specBase + c*T_ + t, sr_n - 1)];
            xi[c] = spec_i[cmin(specBase + c*T_ + t, si_n - 1)];
            Xsh[c][t] = make_float2(xr[c], xi[c]);
        }
        const float wms = mask_s[cmin(maskBase + t, ms_n - 1)];
        const float wmn = mask_n[cmin(maskBase + t, mn_n - 1)];
        sms += wms; smn += wmn;

        int k = 0, ki = 0;
        #pragma unroll
        for (int c = 0; c < C_; ++c) {
            #pragma unroll
            for (int e = c; e < C_; ++e) {
                float re = xr[c]*xr[e] + xi[c]*xi[e];
                asr[k] += wms*re;
                anr[k] += wmn*re;
                if (e != c) {
                    float im = xi[c]*xr[e] - xr[c]*xi[e];
                    asi[ki] += wms*im;
                    ani[ki] += wmn*im;
                    ++ki;
                }
                ++k;
            }
        }
    }

    // ---------------- Phase 2: reduce partials --------------------------------------
    #pragma unroll
    for (int off = 16; off > 0; off >>= 1) {
        #pragma unroll
        for (int k = 0; k < NPAIR; ++k) {
            asr[k] += __shfl_down_sync(0xffffffffu, asr[k], off);
            anr[k] += __shfl_down_sync(0xffffffffu, anr[k], off);
        }
        #pragma unroll
        for (int k = 0; k < NOFF; ++k) {
            asi[k] += __shfl_down_sync(0xffffffffu, asi[k], off);
            ani[k] += __shfl_down_sync(0xffffffffu, ani[k], off);
        }
        sms += __shfl_down_sync(0xffffffffu, sms, off);
        smn += __shfl_down_sync(0xffffffffu, smn, off);
    }
    if ((tid & 31) == 0) {
        #pragma unroll
        for (int k = 0; k < NPAIR; ++k) {
            atomicAdd(&s_acc[k],      asr[k]);
            atomicAdd(&s_acc[36 + k], anr[k]);
        }
        #pragma unroll
        for (int k = 0; k < NOFF; ++k) {
            atomicAdd(&s_acc[21 + k], asi[k]);
            atomicAdd(&s_acc[57 + k], ani[k]);
        }
        atomicAdd(&s_acc[72], sms);
        atomicAdd(&s_acc[73], smn);
    }
    __syncthreads();

    // ---------------- Phase 3: build [psd_n | psd_s], 72-thread GE ------------------
    if (tid < 72) {
        const int r  = tid / 12;
        const int j  = tid % 12;
        const bool isS = (j >= 6);
        const int c2 = isS ? (j - 6) : j;
        const int cc = (r < c2) ? r : c2;
        const int ee = (r < c2) ? c2 : r;
        const int k  = cc*(11 - cc)/2 + ee;
        const int ki = k - (cc + 1);

        const float norm = isS ? (1.0f/(s_acc[72] + PSD_EPS))
                               : (1.0f/(s_acc[73] + PSD_EPS));
        const int reBase = isS ? 0 : 36;
        const int imBase = isS ? 21 : 57;

        float re = s_acc[reBase + k] * norm;
        float im = (r == c2) ? 0.0f : s_acc[imBase + ki] * norm;
        if (r > c2) im = -im;

        if (!isS && r == c2) {
            float trn = (s_acc[36+0] + s_acc[36+6] + s_acc[36+11] +
                         s_acc[36+15] + s_acc[36+18] + s_acc[36+20]) *
                        (1.0f/(s_acc[73] + PSD_EPS));
            re += trn * DIAG_EPS + EPS_;
        }
        M[r][j] = make_float2(re, im);
    }
    __syncthreads();

    const int r = tid / 12;
    const int j = tid % 12;
    #pragma unroll
    for (int kk = 0; kk < C_ - 1; ++kk) {
        if (tid < 72 && j == kk && r > kk)
            fac[r] = cdiv(M[r][kk], M[kk][kk]);
        __syncthreads();
        if (tid < 72 && r > kk) {
            float2 f = fac[r];
            float2 p = M[kk][j];
            float2 v = M[r][j];
            v.x -= f.x*p.x - f.y*p.y;
            v.y -= f.x*p.y + f.y*p.x;
            M[r][j] = v;
        }
        __syncthreads();
    }

    if (tid < C_) {
        #pragma unroll
        for (int kk = C_ - 1; kk >= 0; --kk) {
            float2 acc = M[kk][6 + tid];
            #pragma unroll
            for (int i = C_ - 1; i >= 1; --i) {
                if (i > kk) {
                    float2 a = M[kk][i];
                    float2 w = M[i][6 + tid];
                    acc.x -= a.x*w.x - a.y*w.y;
                    acc.y -= a.x*w.y + a.y*w.x;
                }
            }
            M[kk][6 + tid] = cdiv(acc, M[kk][kk]);
        }
    }
    __syncthreads();

    if (tid == 0) {
        float2 tr = make_float2(0.f, 0.f);
        #pragma unroll
        for (int d = 0; d < C_; ++d) { tr.x += M[d][6+d].x; tr.y += M[d][6+d].y; }
        float2 denom = make_float2(tr.x + EPS_, tr.y);
        #pragma unroll
        for (int c = 0; c < C_; ++c) {
            float2 w = cdiv(M[c][6 + 0], denom);   // REF_CHANNEL = 0
            wc[c] = make_float2(w.x, -w.y);        // conj(w)
        }
    }
    __syncthreads();

    // ---------------- Phase 4: beamform, bounds-guarded output ----------------------
    float2 wreg[C_];
    #pragma unroll
    for (int c = 0; c < C_; ++c) wreg[c] = wc[c];

    for (int t = tid; t < T_; t += THREADS) {
        float ar = 0.f, ai = 0.f;
        #pragma unroll
        for (int c = 0; c < C_; ++c) {
            float2 x = Xsh[c][t];
            ar += wreg[c].x*x.x - wreg[c].y*x.y;
            ai += wreg[c].x*x.y + wreg[c].y*x.x;
        }
        const long long e = maskBase + t;          // element index in (B,F,T)
        if (out_mode == 0) {
            // interleaved complex-as-float: out[2e], out[2e+1]
            if (2*e + 1 < out_n) {
                out[2*e]     = ar;
                out[2*e + 1] = ai;
            }
        } else {
            if (e < out_n) out[e] = ar;            // real part only
        }
    }
}

extern "C" void kernel_launch(void* const* d_in, const int* in_sizes, int n_in,
                              void* d_out, int out_size) {
    const long long SPEC_N = (long long)B_ * F_ * C_ * T_;   // 24,600,000
    const long long MASK_N = (long long)B_ * F_ * T_;        //  4,100,000

    // Size-classified assignment with positional fallback, never indexing
    // past n_in. All sizes are forwarded to the kernel for read clamping.
    const float* ptr[4] = {nullptr, nullptr, nullptr, nullptr};
    long long    psz[4] = {1, 1, 1, 1};
    // slots: 0=spec_r 1=spec_i 2=mask_s 3=mask_n
    for (int i = 0; i < n_in; ++i) {
        long long sz = (long long)in_sizes[i];
        const float* p = (const float*)d_in[i];
        if (sz == SPEC_N) {
            if (!ptr[0]) { ptr[0] = p; psz[0] = sz; }
            else if (!ptr[1]) { ptr[1] = p; psz[1] = sz; }
        } else if (sz == MASK_N) {
            if (!ptr[2]) { ptr[2] = p; psz[2] = sz; }
            else if (!ptr[3]) { ptr[3] = p; psz[3] = sz; }
        }
    }
    for (int s = 0; s < 4; ++s) {
        if (!ptr[s]) {
            int i = (s < n_in) ? s : (n_in - 1);
            ptr[s] = (const float*)d_in[i];
            psz[s] = (long long)in_sizes[i];
        }
    }

    const long long on = (long long)out_size;
    const int out_mode = (on >= 2 * MASK_N) ? 0 : 1;

    mvdr_kernel<<<B_ * F_, THREADS>>>(ptr[0], psz[0], ptr[1], psz[1],
                                      ptr[2], psz[2], ptr[3], psz[3],
                                      (float*)d_out, on, out_mode);
}

// round 8
// speedup vs baseline: 1.3359x; 1.3359x over previous
#include <cuda_runtime.h>

#define B_ 4
#define F_ 1025
#define C_ 6
#define T_ 1000
#define P_ 500          // T_/2 float2 positions
#define THREADS 128

#define DIAG_EPS 1e-7f
#define EPS_ 1e-8f
#define PSD_EPS 1e-15f
#define ACC_N 74
// s_acc layout: [0..20] s_re, [21..35] s_im, [36..56] n_re, [57..71] n_im, [72] sum_ms, [73] sum_mn

__device__ __forceinline__ float2 cdiv(float2 a, float2 b) {
    float inv = 1.0f / (b.x*b.x + b.y*b.y);
    return make_float2((a.x*b.x + a.y*b.y)*inv, (a.y*b.x - a.x*b.y)*inv);
}

// One warp-group accumulates pairs (c,e) for c in [CLO,CHI), e in [c,6), both masks.
// NR/NI: number of re/im accumulators. REB/IMB: global base offsets in s_acc.
template<int CLO, int CHI, int NR, int NI, int REB, int IMB, bool SUM_S>
__device__ __forceinline__ void psd_accum(
    const float2* __restrict__ sr2, const float2* __restrict__ si2,
    const float2* __restrict__ ms2, const float2* __restrict__ mn2,
    float* __restrict__ s_acc, int gtid)
{
    float asr[NR], anr[NR], asi[NI], ani[NI];
    #pragma unroll
    for (int k = 0; k < NR; ++k) { asr[k] = 0.f; anr[k] = 0.f; }
    #pragma unroll
    for (int k = 0; k < NI; ++k) { asi[k] = 0.f; ani[k] = 0.f; }
    float msum = 0.f;

    for (int p = gtid; p < P_; p += 64) {
        float2 vr[C_], vi[C_];
        #pragma unroll
        for (int c = CLO; c < C_; ++c) {
            vr[c] = sr2[c*P_ + p];
            vi[c] = si2[c*P_ + p];
        }
        const float2 m_s = ms2[p];
        const float2 m_n = mn2[p];
        msum += SUM_S ? (m_s.x + m_s.y) : (m_n.x + m_n.y);

        int kr = 0, ko = 0;
        #pragma unroll
        for (int c = CLO; c < CHI; ++c) {
            #pragma unroll
            for (int e = c; e < C_; ++e) {
                float re0 = vr[c].x*vr[e].x + vi[c].x*vi[e].x;
                float re1 = vr[c].y*vr[e].y + vi[c].y*vi[e].y;
                asr[kr] += m_s.x*re0 + m_s.y*re1;
                anr[kr] += m_n.x*re0 + m_n.y*re1;
                if (e != c) {
                    float im0 = vi[c].x*vr[e].x - vr[c].x*vi[e].x;
                    float im1 = vi[c].y*vr[e].y - vr[c].y*vi[e].y;
                    asi[ko] += m_s.x*im0 + m_s.y*im1;
                    ani[ko] += m_n.x*im0 + m_n.y*im1;
                    ++ko;
                }
                ++kr;
            }
        }
    }

    #pragma unroll
    for (int off = 16; off > 0; off >>= 1) {
        #pragma unroll
        for (int k = 0; k < NR; ++k) {
            asr[k] += __shfl_down_sync(0xffffffffu, asr[k], off);
            anr[k] += __shfl_down_sync(0xffffffffu, anr[k], off);
        }
        #pragma unroll
        for (int k = 0; k < NI; ++k) {
            asi[k] += __shfl_down_sync(0xffffffffu, asi[k], off);
            ani[k] += __shfl_down_sync(0xffffffffu, ani[k], off);
        }
        msum += __shfl_down_sync(0xffffffffu, msum, off);
    }
    if ((threadIdx.x & 31) == 0) {
        #pragma unroll
        for (int k = 0; k < NR; ++k) {
            atomicAdd(&s_acc[REB + k],      asr[k]);
            atomicAdd(&s_acc[36 + REB + k], anr[k]);
        }
        #pragma unroll
        for (int k = 0; k < NI; ++k) {
            atomicAdd(&s_acc[21 + IMB + k], asi[k]);
            atomicAdd(&s_acc[57 + IMB + k], ani[k]);
        }
        atomicAdd(&s_acc[SUM_S ? 72 : 73], msum);
    }
}

__global__ __launch_bounds__(THREADS, 6)
void mvdr_kernel(const float* __restrict__ spec_r,
                 const float* __restrict__ spec_i,
                 const float* __restrict__ mask_s,
                 const float* __restrict__ mask_n,
                 float* __restrict__ out, int out_mode)
{
    __shared__ float  s_acc[ACC_N];
    __shared__ float2 M[C_][2*C_];
    __shared__ float2 fac[C_];
    __shared__ float2 wc[C_];

    const int bf  = blockIdx.x;
    const int tid = threadIdx.x;

    const float2* sr2 = (const float2*)spec_r + (size_t)bf * (C_*P_);
    const float2* si2 = (const float2*)spec_i + (size_t)bf * (C_*P_);
    const float2* ms2 = (const float2*)mask_s + (size_t)bf * P_;
    const float2* mn2 = (const float2*)mask_n + (size_t)bf * P_;

    if (tid < ACC_N) s_acc[tid] = 0.0f;
    __syncthreads();

    // ---- Phase 1+2: split pair accumulation across warp-groups ----
    // group0 (warps 0-1): c in {0,1}: 11 re + 9 im.  group1 (warps 2-3): c in {2..5}: 10 re + 6 im.
    if (tid < 64)
        psd_accum<0, 2, 11, 9, 0, 0, true >(sr2, si2, ms2, mn2, s_acc, tid);
    else
        psd_accum<2, 6, 10, 6, 11, 9, false>(sr2, si2, ms2, mn2, s_acc, tid - 64);
    __syncthreads();

    // ---- Phase 3: build [psd_n | psd_s], 72-thread Gaussian elimination ----
    if (tid < 72) {
        const int r  = tid / 12;
        const int j  = tid % 12;
        const bool isS = (j >= 6);
        const int c2 = isS ? (j - 6) : j;
        const int cc = (r < c2) ? r : c2;
        const int ee = (r < c2) ? c2 : r;
        const int k  = cc*(11 - cc)/2 + ee;
        const int ki = k - (cc + 1);

        const float norm = isS ? (1.0f/(s_acc[72] + PSD_EPS))
                               : (1.0f/(s_acc[73] + PSD_EPS));
        const int reBase = isS ? 0 : 36;
        const int imBase = isS ? 21 : 57;

        float re = s_acc[reBase + k] * norm;
        float im = (r == c2) ? 0.0f : s_acc[imBase + ki] * norm;
        if (r > c2) im = -im;

        if (!isS && r == c2) {
            float trn = (s_acc[36+0] + s_acc[36+6] + s_acc[36+11] +
                         s_acc[36+15] + s_acc[36+18] + s_acc[36+20]) *
                        (1.0f/(s_acc[73] + PSD_EPS));
            re += trn * DIAG_EPS + EPS_;
        }
        M[r][j] = make_float2(re, im);
    }
    __syncthreads();

    const int r = tid / 12;
    const int j = tid % 12;
    #pragma unroll
    for (int kk = 0; kk < C_ - 1; ++kk) {
        if (tid < 72 && j == kk && r > kk)
            fac[r] = cdiv(M[r][kk], M[kk][kk]);
        __syncthreads();
        if (tid < 72 && r > kk) {
            float2 f = fac[r];
            float2 p = M[kk][j];
            float2 v = M[r][j];
            v.x -= f.x*p.x - f.y*p.y;
            v.y -= f.x*p.y + f.y*p.x;
            M[r][j] = v;
        }
        __syncthreads();
    }

    if (tid < C_) {
        #pragma unroll
        for (int kk = C_ - 1; kk >= 0; --kk) {
            float2 acc = M[kk][6 + tid];
            #pragma unroll
            for (int i = C_ - 1; i >= 1; --i) {
                if (i > kk) {
                    float2 a = M[kk][i];
                    float2 w = M[i][6 + tid];
                    acc.x -= a.x*w.x - a.y*w.y;
                    acc.y -= a.x*w.y + a.y*w.x;
                }
            }
            M[kk][6 + tid] = cdiv(acc, M[kk][kk]);
        }
    }
    __syncthreads();

    if (tid == 0) {
        float2 tr = make_float2(0.f, 0.f);
        #pragma unroll
        for (int d = 0; d < C_; ++d) { tr.x += M[d][6+d].x; tr.y += M[d][6+d].y; }
        float2 denom = make_float2(tr.x + EPS_, tr.y);
        #pragma unroll
        for (int c = 0; c < C_; ++c) {
            float2 w = cdiv(M[c][6 + 0], denom);   // REF_CHANNEL = 0
            wc[c] = make_float2(w.x, -w.y);        // conj(w)
        }
    }
    __syncthreads();

    // ---- Phase 4: beamform, re-reading X from global (L2-resident) ----
    float2 wreg[C_];
    #pragma unroll
    for (int c = 0; c < C_; ++c) wreg[c] = wc[c];

    if (out_mode == 0) {
        float4* o4 = (float4*)out + (size_t)bf * P_;
        for (int p = tid; p < P_; p += THREADS) {
            float ar0 = 0.f, ai0 = 0.f, ar1 = 0.f, ai1 = 0.f;
            #pragma unroll
            for (int c = 0; c < C_; ++c) {
                float2 xr = sr2[c*P_ + p];
                float2 xi = si2[c*P_ + p];
                ar0 += wreg[c].x*xr.x - wreg[c].y*xi.x;
                ai0 += wreg[c].x*xi.x + wreg[c].y*xr.x;
                ar1 += wreg[c].x*xr.y - wreg[c].y*xi.y;
                ai1 += wreg[c].x*xi.y + wreg[c].y*xr.y;
            }
            o4[p] = make_float4(ar0, ai0, ar1, ai1);
        }
    } else {
        float* o = out + (size_t)bf * T_;
        for (int p = tid; p < P_; p += THREADS) {
            float ar0 = 0.f, ar1 = 0.f;
            #pragma unroll
            for (int c = 0; c < C_; ++c) {
                float2 xr = sr2[c*P_ + p];
                float2 xi = si2[c*P_ + p];
                ar0 += wreg[c].x*xr.x - wreg[c].y*xi.x;
                ar1 += wreg[c].x*xr.y - wreg[c].y*xi.y;
            }
            o[2*p]     = ar0;
            o[2*p + 1] = ar1;
        }
    }
}

extern "C" void kernel_launch(void* const* d_in, const int* in_sizes, int n_in,
                              void* d_out, int out_size) {
    const long long SPEC_N = (long long)B_ * F_ * C_ * T_;   // 24,600,000
    const long long MASK_N = (long long)B_ * F_ * T_;        //  4,100,000

    const float* ptr[4] = {nullptr, nullptr, nullptr, nullptr};
    for (int i = 0; i < n_in; ++i) {
        long long sz = (long long)in_sizes[i];
        const float* p = (const float*)d_in[i];
        if (sz == SPEC_N) {
            if (!ptr[0]) ptr[0] = p; else if (!ptr[1]) ptr[1] = p;
        } else if (sz == MASK_N) {
            if (!ptr[2]) ptr[2] = p; else if (!ptr[3]) ptr[3] = p;
        }
    }
    for (int s = 0; s < 4; ++s) {
        if (!ptr[s]) {
            int i = (s < n_in) ? s : (n_in - 1);
            ptr[s] = (const float*)d_in[i];
        }
    }

    const int out_mode = ((long long)out_size >= 2 * MASK_N) ? 0 : 1;

    mvdr_kernel<<<B_ * F_, THREADS>>>(ptr[0], ptr[1], ptr[2], ptr[3],
                                      (float*)d_out, out_mode);
}

// round 10
// speedup vs baseline: 1.3958x; 1.0448x over previous
#include <cuda_runtime.h>

#define B_ 4
#define F_ 1025
#define C_ 6
#define T_ 1000
#define P_ 500          // T_/2 float2 positions
#define CHUNK 125       // packed positions per staged chunk (4 chunks)
#define THREADS 128

#define DIAG_EPS 1e-7f
#define EPS_ 1e-8f
#define PSD_EPS 1e-15f
#define ACC_N 74
// s_acc: [0..20] s_re, [21..35] s_im, [36..56] n_re, [57..71] n_im, [72] sum_ms, [73] sum_mn

__device__ __forceinline__ float2 cdiv(float2 a, float2 b) {
    float inv = 1.0f / (b.x*b.x + b.y*b.y);
    return make_float2((a.x*b.x + a.y*b.y)*inv, (a.y*b.x - a.x*b.y)*inv);
}

// One warp accumulates pairs (c,e), c in [CLO,CHI), e in [c,6), both masks, over one chunk.
template<int CLO, int CHI, bool SUMM>
__device__ __forceinline__ void psd_chunk(
    const float2 (*XR)[CHUNK], const float2 (*XI)[CHUNK],
    const float2* msb, const float2* mnb, int lane,
    float* asr, float* anr, float* asi, float* ani, float& sms, float& smn)
{
    for (int p = lane; p < CHUNK; p += 32) {
        float2 vr[C_], vi[C_];
        #pragma unroll
        for (int c = CLO; c < C_; ++c) { vr[c] = XR[c][p]; vi[c] = XI[c][p]; }
        const float2 m_s = msb[p];
        const float2 m_n = mnb[p];
        if (SUMM) { sms += m_s.x + m_s.y; smn += m_n.x + m_n.y; }

        int kr = 0, ko = 0;
        #pragma unroll
        for (int c = CLO; c < CHI; ++c) {
            #pragma unroll
            for (int e = c; e < C_; ++e) {
                float re0 = vr[c].x*vr[e].x + vi[c].x*vi[e].x;
                float re1 = vr[c].y*vr[e].y + vi[c].y*vi[e].y;
                asr[kr] += m_s.x*re0 + m_s.y*re1;
                anr[kr] += m_n.x*re0 + m_n.y*re1;
                if (e != c) {
                    float im0 = vi[c].x*vr[e].x - vr[c].x*vi[e].x;
                    float im1 = vi[c].y*vr[e].y - vr[c].y*vi[e].y;
                    asi[ko] += m_s.x*im0 + m_s.y*im1;
                    ani[ko] += m_n.x*im0 + m_n.y*im1;
                    ++ko;
                }
                ++kr;
            }
        }
    }
}

// lane0 of the owning warp writes its reduced accumulators straight to s_acc.
template<int CLO, int CHI, bool SUMM>
__device__ __forceinline__ void store_acc(
    float* s_acc, const float* asr, const float* anr,
    const float* asi, const float* ani, float sms, float smn)
{
    int kr = 0, ko = 0;
    #pragma unroll
    for (int c = CLO; c < CHI; ++c) {
        #pragma unroll
        for (int e = c; e < C_; ++e) {
            const int kg = c*(11 - c)/2 + e;
            s_acc[kg]      = asr[kr];
            s_acc[36 + kg] = anr[kr];
            if (e != c) {
                const int kig = kg - (c + 1);
                s_acc[21 + kig] = asi[ko];
                s_acc[57 + kig] = ani[ko];
                ++ko;
            }
            ++kr;
        }
    }
    if (SUMM) { s_acc[72] = sms; s_acc[73] = smn; }
}

__global__ __launch_bounds__(THREADS, 7)
void mvdr_kernel(const float* __restrict__ spec_r,
                 const float* __restrict__ spec_i,
                 const float* __restrict__ mask_s,
                 const float* __restrict__ mask_n,
                 float* __restrict__ out, int out_mode)
{
    __shared__ float2 XR[C_][CHUNK];    // 6000 B
    __shared__ float2 XI[C_][CHUNK];    // 6000 B
    __shared__ float2 msb[CHUNK];       // 1000 B
    __shared__ float2 mnb[CHUNK];       // 1000 B
    __shared__ float  s_acc[ACC_N];
    __shared__ float2 M[C_][2*C_];
    __shared__ float2 fac[C_];
    __shared__ float2 wc[C_];

    const int bf   = blockIdx.x;
    const int tid  = threadIdx.x;
    const int lane = tid & 31;
    const int wid  = tid >> 5;

    const float2* sr2 = (const float2*)spec_r + (size_t)bf * (C_*P_);
    const float2* si2 = (const float2*)spec_i + (size_t)bf * (C_*P_);
    const float2* ms2 = (const float2*)mask_s + (size_t)bf * P_;
    const float2* mn2 = (const float2*)mask_n + (size_t)bf * P_;

    // Per-warp accumulators (uniform max sizes; unused slots stay 0).
    float asr[6], anr[6], asi[5], ani[5];
    #pragma unroll
    for (int k = 0; k < 6; ++k) { asr[k] = 0.f; anr[k] = 0.f; }
    #pragma unroll
    for (int k = 0; k < 5; ++k) { asi[k] = 0.f; ani[k] = 0.f; }
    float sms = 0.f, smn = 0.f;

    // ---- Phase 1: staged chunks; each warp owns a disjoint pair set ----
    #pragma unroll 1
    for (int ch = 0; ch < P_ / CHUNK; ++ch) {
        const int base = ch * CHUNK;
        if (tid < CHUNK) {
            #pragma unroll
            for (int c = 0; c < C_; ++c) {
                XR[c][tid] = sr2[c*P_ + base + tid];
                XI[c][tid] = si2[c*P_ + base + tid];
            }
            msb[tid] = ms2[base + tid];
            mnb[tid] = mn2[base + tid];
        }
        __syncthreads();
        if      (wid == 0) psd_chunk<0,1,false>(XR, XI, msb, mnb, lane, asr, anr, asi, ani, sms, smn);
        else if (wid == 1) psd_chunk<1,2,false>(XR, XI, msb, mnb, lane, asr, anr, asi, ani, sms, smn);
        else if (wid == 2) psd_chunk<2,3,true >(XR, XI, msb, mnb, lane, asr, anr, asi, ani, sms, smn);
        else               psd_chunk<3,6,false>(XR, XI, msb, mnb, lane, asr, anr, asi, ani, sms, smn);
        __syncthreads();
    }

    // ---- Phase 2: warp-local shuffle reduction, direct stores (no atomics) ----
    #pragma unroll
    for (int off = 16; off > 0; off >>= 1) {
        #pragma unroll
        for (int k = 0; k < 6; ++k) {
            asr[k] += __shfl_down_sync(0xffffffffu, asr[k], off);
            anr[k] += __shfl_down_sync(0xffffffffu, anr[k], off);
        }
        #pragma unroll
        for (int k = 0; k < 5; ++k) {
            asi[k] += __shfl_down_sync(0xffffffffu, asi[k], off);
            ani[k] += __shfl_down_sync(0xffffffffu, ani[k], off);
        }
        sms += __shfl_down_sync(0xffffffffu, sms, off);
        smn += __shfl_down_sync(0xffffffffu, smn, off);
    }
    if (lane == 0) {
        if      (wid == 0) store_acc<0,1,false>(s_acc, asr, anr, asi, ani, sms, smn);
        else if (wid == 1) store_acc<1,2,false>(s_acc, asr, anr, asi, ani, sms, smn);
        else if (wid == 2) store_acc<2,3,true >(s_acc, asr, anr, asi, ani, sms, smn);
        else               store_acc<3,6,false>(s_acc, asr, anr, asi, ani, sms, smn);
    }
    __syncthreads();

    // ---- Phase 3: build [psd_n | psd_s], 72-thread Gaussian elimination ----
    if (tid < 72) {
        const int r  = tid / 12;
        const int j  = tid % 12;
        const bool isS = (j >= 6);
        const int c2 = isS ? (j - 6) : j;
        const int cc = (r < c2) ? r : c2;
        const int ee = (r < c2) ? c2 : r;
        const int k  = cc*(11 - cc)/2 + ee;
        const int ki = k - (cc + 1);

        const float norm = isS ? (1.0f/(s_acc[72] + PSD_EPS))
                               : (1.0f/(s_acc[73] + PSD_EPS));
        const int reBase = isS ? 0 : 36;
        const int imBase = isS ? 21 : 57;

        float re = s_acc[reBase + k] * norm;
        float im = (r == c2) ? 0.0f : s_acc[imBase + ki] * norm;
        if (r > c2) im = -im;

        if (!isS && r == c2) {
            float trn = (s_acc[36+0] + s_acc[36+6] + s_acc[36+11] +
                         s_acc[36+15] + s_acc[36+18] + s_acc[36+20]) *
                        (1.0f/(s_acc[73] + PSD_EPS));
            re += trn * DIAG_EPS + EPS_;
        }
        M[r][j] = make_float2(re, im);
    }
    __syncthreads();

    const int r = tid / 12;
    const int j = tid % 12;
    #pragma unroll
    for (int kk = 0; kk < C_ - 1; ++kk) {
        if (tid < 72 && j == kk && r > kk)
            fac[r] = cdiv(M[r][kk], M[kk][kk]);
        __syncthreads();
        if (tid < 72 && r > kk) {
            float2 f = fac[r];
            float2 p = M[kk][j];
            float2 v = M[r][j];
            v.x -= f.x*p.x - f.y*p.y;
            v.y -= f.x*p.y + f.y*p.x;
            M[r][j] = v;
        }
        __syncthreads();
    }

    if (tid < C_) {
        #pragma unroll
        for (int kk = C_ - 1; kk >= 0; --kk) {
            float2 acc = M[kk][6 + tid];
            #pragma unroll
            for (int i = C_ - 1; i >= 1; --i) {
                if (i > kk) {
                    float2 a = M[kk][i];
                    float2 w = M[i][6 + tid];
                    acc.x -= a.x*w.x - a.y*w.y;
                    acc.y -= a.x*w.y + a.y*w.x;
                }
            }
            M[kk][6 + tid] = cdiv(acc, M[kk][kk]);
        }
    }
    __syncthreads();

    if (tid == 0) {
        float2 tr = make_float2(0.f, 0.f);
        #pragma unroll
        for (int d = 0; d < C_; ++d) { tr.x += M[d][6+d].x; tr.y += M[d][6+d].y; }
        float2 denom = make_float2(tr.x + EPS_, tr.y);
        #pragma unroll
        for (int c = 0; c < C_; ++c) {
            float2 w = cdiv(M[c][6 + 0], denom);   // REF_CHANNEL = 0
            wc[c] = make_float2(w.x, -w.y);        // conj(w)
        }
    }
    __syncthreads();

    // ---- Phase 4: beamform, re-reading X from global (L2-resident) ----
    float2 wreg[C_];
    #pragma unroll
    for (int c = 0; c < C_; ++c) wreg[c] = wc[c];

    if (out_mode == 0) {
        float4* o4 = (float4*)out + (size_t)bf * P_;
        for (int p = tid; p < P_; p += THREADS) {
            float ar0 = 0.f, ai0 = 0.f, ar1 = 0.f, ai1 = 0.f;
            #pragma unroll
            for (int c = 0; c < C_; ++c) {
                float2 xr = sr2[c*P_ + p];
                float2 xi = si2[c*P_ + p];
                ar0 += wreg[c].x*xr.x - wreg[c].y*xi.x;
                ai0 += wreg[c].x*xi.x + wreg[c].y*xr.x;
                ar1 += wreg[c].x*xr.y - wreg[c].y*xi.y;
                ai1 += wreg[c].x*xi.y + wreg[c].y*xr.y;
            }
            o4[p] = make_float4(ar0, ai0, ar1, ai1);
        }
    } else {
        float* o = out + (size_t)bf * T_;
        for (int p = tid; p < P_; p += THREADS) {
            float ar0 = 0.f, ar1 = 0.f;
            #pragma unroll
            for (int c = 0; c < C_; ++c) {
                float2 xr = sr2[c*P_ + p];
                float2 xi = si2[c*P_ + p];
                ar0 += wreg[c].x*xr.x - wreg[c].y*xi.x;
                ar1 += wreg[c].x*xr.y - wreg[c].y*xi.y;
            }
            o[2*p]     = ar0;
            o[2*p + 1] = ar1;
        }
    }
}

extern "C" void kernel_launch(void* const* d_in, const int* in_sizes, int n_in,
                              void* d_out, int out_size) {
    const long long SPEC_N = (long long)B_ * F_ * C_ * T_;   // 24,600,000
    const long long MASK_N = (long long)B_ * F_ * T_;        //  4,100,000

    const float* ptr[4] = {nullptr, nullptr, nullptr, nullptr};
    for (int i = 0; i < n_in; ++i) {
        long long sz = (long long)in_sizes[i];
        const float* p = (const float*)d_in[i];
        if (sz == SPEC_N) {
            if (!ptr[0]) ptr[0] = p; else if (!ptr[1]) ptr[1] = p;
        } else if (sz == MASK_N) {
            if (!ptr[2]) ptr[2] = p; else if (!ptr[3]) ptr[3] = p;
        }
    }
    for (int s = 0; s < 4; ++s) {
        if (!ptr[s]) {
            int i = (s < n_in) ? s : (n_in - 1);
            ptr[s] = (const float*)d_in[i];
        }
    }

    const int out_mode = ((long long)out_size >= 2 * MASK_N) ? 0 : 1;

    mvdr_kernel<<<B_ * F_, THREADS>>>(ptr[0], ptr[1], ptr[2], ptr[3],
                                      (float*)d_out, out_mode);
}

// round 12
// speedup vs baseline: 1.4444x; 1.0348x over previous
#include <cuda_runtime.h>

#define B_ 4
#define F_ 1025
#define C_ 6
#define T_ 1000
#define QN 250          // T_/4 float4 quad positions
#define THREADS 128

#define DIAG_EPS 1e-7f
#define EPS_ 1e-8f
#define PSD_EPS 1e-15f
#define ACC_N 74
// s_acc: [0..20] s_re, [21..35] s_im, [36..56] n_re, [57..71] n_im, [72] sum_ms, [73] sum_mn

__device__ __forceinline__ float2 cdiv(float2 a, float2 b) {
    float inv = 1.0f / (b.x*b.x + b.y*b.y);
    return make_float2((a.x*b.x + a.y*b.y)*inv, (a.y*b.x - a.x*b.y)*inv);
}

// One warp accumulates pairs (c,e), c in [CLO,CHI), e in [c,6), both masks,
// reading X directly from global as float4 (4 time steps per iteration).
template<int CLO, int CHI, bool SUMM>
__device__ __forceinline__ void psd_direct(
    const float4* __restrict__ sr4, const float4* __restrict__ si4,
    const float4* __restrict__ ms4, const float4* __restrict__ mn4, int lane,
    float* asr, float* anr, float* asi, float* ani, float& sms, float& smn)
{
    for (int q = lane; q < QN; q += 32) {
        float4 xr[C_], xi[C_];
        #pragma unroll
        for (int c = CLO; c < C_; ++c) {
            xr[c] = sr4[c*QN + q];
            xi[c] = si4[c*QN + q];
        }
        const float4 m_s = ms4[q];
        const float4 m_n = mn4[q];
        if (SUMM) {
            sms += (m_s.x + m_s.y) + (m_s.z + m_s.w);
            smn += (m_n.x + m_n.y) + (m_n.z + m_n.w);
        }

        int kr = 0, ko = 0;
        #pragma unroll
        for (int c = CLO; c < CHI; ++c) {
            #pragma unroll
            for (int e = c; e < C_; ++e) {
                float r0 = xr[c].x*xr[e].x + xi[c].x*xi[e].x;
                float r1 = xr[c].y*xr[e].y + xi[c].y*xi[e].y;
                float r2 = xr[c].z*xr[e].z + xi[c].z*xi[e].z;
                float r3 = xr[c].w*xr[e].w + xi[c].w*xi[e].w;
                asr[kr] += m_s.x*r0 + m_s.y*r1 + m_s.z*r2 + m_s.w*r3;
                anr[kr] += m_n.x*r0 + m_n.y*r1 + m_n.z*r2 + m_n.w*r3;
                if (e != c) {
                    float i0 = xi[c].x*xr[e].x - xr[c].x*xi[e].x;
                    float i1 = xi[c].y*xr[e].y - xr[c].y*xi[e].y;
                    float i2 = xi[c].z*xr[e].z - xr[c].z*xi[e].z;
                    float i3 = xi[c].w*xr[e].w - xr[c].w*xi[e].w;
                    asi[ko] += m_s.x*i0 + m_s.y*i1 + m_s.z*i2 + m_s.w*i3;
                    ani[ko] += m_n.x*i0 + m_n.y*i1 + m_n.z*i2 + m_n.w*i3;
                    ++ko;
                }
                ++kr;
            }
        }
    }
}

// lane0 of the owning warp writes its reduced accumulators straight to s_acc.
template<int CLO, int CHI, bool SUMM>
__device__ __forceinline__ void store_acc(
    float* s_acc, const float* asr, const float* anr,
    const float* asi, const float* ani, float sms, float smn)
{
    int kr = 0, ko = 0;
    #pragma unroll
    for (int c = CLO; c < CHI; ++c) {
        #pragma unroll
        for (int e = c; e < C_; ++e) {
            const int kg = c*(11 - c)/2 + e;
            s_acc[kg]      = asr[kr];
            s_acc[36 + kg] = anr[kr];
            if (e != c) {
                const int kig = kg - (c + 1);
                s_acc[21 + kig] = asi[ko];
                s_acc[57 + kig] = ani[ko];
                ++ko;
            }
            ++kr;
        }
    }
    if (SUMM) { s_acc[72] = sms; s_acc[73] = smn; }
}

__global__ __launch_bounds__(THREADS, 6)
void mvdr_kernel(const float* __restrict__ spec_r,
                 const float* __restrict__ spec_i,
                 const float* __restrict__ mask_s,
                 const float* __restrict__ mask_n,
                 float* __restrict__ out, int out_mode)
{
    __shared__ float  s_acc[ACC_N];
    __shared__ float2 M[C_][2*C_];
    __shared__ float2 fac[C_];
    __shared__ float2 wc[C_];

    const int bf   = blockIdx.x;
    const int tid  = threadIdx.x;
    const int lane = tid & 31;
    const int wid  = tid >> 5;

    const float4* sr4 = (const float4*)(spec_r + (size_t)bf * (C_*T_));
    const float4* si4 = (const float4*)(spec_i + (size_t)bf * (C_*T_));
    const float4* ms4 = (const float4*)(mask_s + (size_t)bf * T_);
    const float4* mn4 = (const float4*)(mask_n + (size_t)bf * T_);

    float asr[6], anr[6], asi[5], ani[5];
    #pragma unroll
    for (int k = 0; k < 6; ++k) { asr[k] = 0.f; anr[k] = 0.f; }
    #pragma unroll
    for (int k = 0; k < 5; ++k) { asi[k] = 0.f; ani[k] = 0.f; }
    float sms = 0.f, smn = 0.f;

    // ---- Phase 1: direct-global float4 accumulation; warp-owned pair sets ----
    if      (wid == 0) psd_direct<0,1,false>(sr4, si4, ms4, mn4, lane, asr, anr, asi, ani, sms, smn);
    else if (wid == 1) psd_direct<1,2,false>(sr4, si4, ms4, mn4, lane, asr, anr, asi, ani, sms, smn);
    else if (wid == 2) psd_direct<2,3,true >(sr4, si4, ms4, mn4, lane, asr, anr, asi, ani, sms, smn);
    else               psd_direct<3,6,false>(sr4, si4, ms4, mn4, lane, asr, anr, asi, ani, sms, smn);

    // ---- Phase 2: warp-local shuffle reduction, direct stores (no atomics) ----
    #pragma unroll
    for (int off = 16; off > 0; off >>= 1) {
        #pragma unroll
        for (int k = 0; k < 6; ++k) {
            asr[k] += __shfl_down_sync(0xffffffffu, asr[k], off);
            anr[k] += __shfl_down_sync(0xffffffffu, anr[k], off);
        }
        #pragma unroll
        for (int k = 0; k < 5; ++k) {
            asi[k] += __shfl_down_sync(0xffffffffu, asi[k], off);
            ani[k] += __shfl_down_sync(0xffffffffu, ani[k], off);
        }
        sms += __shfl_down_sync(0xffffffffu, sms, off);
        smn += __shfl_down_sync(0xffffffffu, smn, off);
    }
    if (lane == 0) {
        if      (wid == 0) store_acc<0,1,false>(s_acc, asr, anr, asi, ani, sms, smn);
        else if (wid == 1) store_acc<1,2,false>(s_acc, asr, anr, asi, ani, sms, smn);
        else if (wid == 2) store_acc<2,3,true >(s_acc, asr, anr, asi, ani, sms, smn);
        else               store_acc<3,6,false>(s_acc, asr, anr, asi, ani, sms, smn);
    }
    __syncthreads();

    // ---- Phase 3: build [psd_n | psd_s], 72-thread Gaussian elimination ----
    if (tid < 72) {
        const int r  = tid / 12;
        const int j  = tid % 12;
        const bool isS = (j >= 6);
        const int c2 = isS ? (j - 6) : j;
        const int cc = (r < c2) ? r : c2;
        const int ee = (r < c2) ? c2 : r;
        const int k  = cc*(11 - cc)/2 + ee;
        const int ki = k - (cc + 1);

        const float norm = isS ? (1.0f/(s_acc[72] + PSD_EPS))
                               : (1.0f/(s_acc[73] + PSD_EPS));
        const int reBase = isS ? 0 : 36;
        const int imBase = isS ? 21 : 57;

        float re = s_acc[reBase + k] * norm;
        float im = (r == c2) ? 0.0f : s_acc[imBase + ki] * norm;
        if (r > c2) im = -im;

        if (!isS && r == c2) {
            float trn = (s_acc[36+0] + s_acc[36+6] + s_acc[36+11] +
                         s_acc[36+15] + s_acc[36+18] + s_acc[36+20]) *
                        (1.0f/(s_acc[73] + PSD_EPS));
            re += trn * DIAG_EPS + EPS_;
        }
        M[r][j] = make_float2(re, im);
    }
    __syncthreads();

    const int r = tid / 12;
    const int j = tid % 12;
    #pragma unroll
    for (int kk = 0; kk < C_ - 1; ++kk) {
        if (tid < 72 && j == kk && r > kk)
            fac[r] = cdiv(M[r][kk], M[kk][kk]);
        __syncthreads();
        if (tid < 72 && r > kk) {
            float2 f = fac[r];
            float2 p = M[kk][j];
            float2 v = M[r][j];
            v.x -= f.x*p.x - f.y*p.y;
            v.y -= f.x*p.y + f.y*p.x;
            M[r][j] = v;
        }
        __syncthreads();
    }

    if (tid < C_) {
        #pragma unroll
        for (int kk = C_ - 1; kk >= 0; --kk) {
            float2 acc = M[kk][6 + tid];
            #pragma unroll
            for (int i = C_ - 1; i >= 1; --i) {
                if (i > kk) {
                    float2 a = M[kk][i];
                    float2 w = M[i][6 + tid];
                    acc.x -= a.x*w.x - a.y*w.y;
                    acc.y -= a.x*w.y + a.y*w.x;
                }
            }
            M[kk][6 + tid] = cdiv(acc, M[kk][kk]);
        }
    }
    __syncthreads();

    if (tid == 0) {
        float2 tr = make_float2(0.f, 0.f);
        #pragma unroll
        for (int d = 0; d < C_; ++d) { tr.x += M[d][6+d].x; tr.y += M[d][6+d].y; }
        float2 denom = make_float2(tr.x + EPS_, tr.y);
        #pragma unroll
        for (int c = 0; c < C_; ++c) {
            float2 w = cdiv(M[c][6 + 0], denom);   // REF_CHANNEL = 0
            wc[c] = make_float2(w.x, -w.y);        // conj(w)
        }
    }
    __syncthreads();

    // ---- Phase 4: beamform, float4 re-read (L1/L2-resident) ----
    float2 wreg[C_];
    #pragma unroll
    for (int c = 0; c < C_; ++c) wreg[c] = wc[c];

    if (out_mode == 0) {
        float4* o4 = (float4*)out + (size_t)bf * (T_/2);
        for (int q = tid; q < QN; q += THREADS) {
            float4 ar = make_float4(0.f, 0.f, 0.f, 0.f);
            float4 ai = make_float4(0.f, 0.f, 0.f, 0.f);
            #pragma unroll
            for (int c = 0; c < C_; ++c) {
                float4 xr = sr4[c*QN + q];
                float4 xi = si4[c*QN + q];
                ar.x += wreg[c].x*xr.x - wreg[c].y*xi.x;
                ai.x += wreg[c].x*xi.x + wreg[c].y*xr.x;
                ar.y += wreg[c].x*xr.y - wreg[c].y*xi.y;
                ai.y += wreg[c].x*xi.y + wreg[c].y*xr.y;
                ar.z += wreg[c].x*xr.z - wreg[c].y*xi.z;
                ai.z += wreg[c].x*xi.z + wreg[c].y*xr.z;
                ar.w += wreg[c].x*xr.w - wreg[c].y*xi.w;
                ai.w += wreg[c].x*xi.w + wreg[c].y*xr.w;
            }
            o4[2*q]     = make_float4(ar.x, ai.x, ar.y, ai.y);
            o4[2*q + 1] = make_float4(ar.z, ai.z, ar.w, ai.w);
        }
    } else {
        float4* o4 = (float4*)(out + (size_t)bf * T_);
        for (int q = tid; q < QN; q += THREADS) {
            float4 ar = make_float4(0.f, 0.f, 0.f, 0.f);
            #pragma unroll
            for (int c = 0; c < C_; ++c) {
                float4 xr = sr4[c*QN + q];
                float4 xi = si4[c*QN + q];
                ar.x += wreg[c].x*xr.x - wreg[c].y*xi.x;
                ar.y += wreg[c].x*xr.y - wreg[c].y*xi.y;
                ar.z += wreg[c].x*xr.z - wreg[c].y*xi.z;
                ar.w += wreg[c].x*xr.w - wreg[c].y*xi.w;
            }
            o4[q] = ar;
        }
    }
}

extern "C" void kernel_launch(void* const* d_in, const int* in_sizes, int n_in,
                              void* d_out, int out_size) {
    const long long SPEC_N = (long long)B_ * F_ * C_ * T_;   // 24,600,000
    const long long MASK_N = (long long)B_ * F_ * T_;        //  4,100,000

    const float* ptr[4] = {nullptr, nullptr, nullptr, nullptr};
    for (int i = 0; i < n_in; ++i) {
        long long sz = (long long)in_sizes[i];
        const float* p = (const float*)d_in[i];
        if (sz == SPEC_N) {
            if (!ptr[0]) ptr[0] = p; else if (!ptr[1]) ptr[1] = p;
        } else if (sz == MASK_N) {
            if (!ptr[2]) ptr[2] = p; else if (!ptr[3]) ptr[3] = p;
        }
    }
    for (int s = 0; s < 4; ++s) {
        if (!ptr[s]) {
            int i = (s < n_in) ? s : (n_in - 1);
            ptr[s] = (const float*)d_in[i];
        }
    }

    const int out_mode = ((long long)out_size >= 2 * MASK_N) ? 0 : 1;

    mvdr_kernel<<<B_ * F_, THREADS>>>(ptr[0], ptr[1], ptr[2], ptr[3],
                                      (float*)d_out, out_mode);
}

// round 16
// speedup vs baseline: 1.4709x; 1.0183x over previous
#include <cuda_runtime.h>

#define B_ 4
#define F_ 1025
#define C_ 6
#define T_ 1000
#define P_ 500          // T_/2 float2 positions
#define THREADS 128

#define DIAG_EPS 1e-7f
#define EPS_ 1e-8f
#define PSD_EPS 1e-15f
#define ACC_N 74
// s_acc: [0..20] s_re, [21..35] s_im, [36..56] n_re, [57..71] n_im, [72] sum_ms, [73] sum_mn

__device__ __forceinline__ float2 cdiv(float2 a, float2 b) {
    float inv = 1.0f / (b.x*b.x + b.y*b.y);
    return make_float2((a.x*b.x + a.y*b.y)*inv, (a.y*b.x - a.x*b.y)*inv);
}

// Per-warp pair configuration via constexpr FUNCTIONS (nvcc rejects device
// ODR-use of static constexpr data arrays in template specializations).
// All call sites sit inside fully-unrolled loops, so these fold to literals.
template<int WID> struct WCfg;
template<> struct WCfg<0> {                      // pairs within {0,1,2}
    static constexpr int NCH = 3, NP = 6;
    static constexpr bool SUMM = false;
    static constexpr __host__ __device__ int ch(int i){ const int v[3]={0,1,2}; return v[i]; }
    static constexpr __host__ __device__ int pa(int k){ const int v[6]={0,0,0,1,1,2}; return v[k]; }
    static constexpr __host__ __device__ int pb(int k){ const int v[6]={0,1,2,1,2,2}; return v[k]; }
    static constexpr __host__ __device__ int gc(int k){ const int v[6]={0,0,0,1,1,2}; return v[k]; }
    static constexpr __host__ __device__ int ge(int k){ const int v[6]={0,1,2,1,2,2}; return v[k]; }
};
template<> struct WCfg<1> {                      // pairs within {3,4,5}
    static constexpr int NCH = 3, NP = 6;
    static constexpr bool SUMM = false;
    static constexpr __host__ __device__ int ch(int i){ const int v[3]={3,4,5}; return v[i]; }
    static constexpr __host__ __device__ int pa(int k){ const int v[6]={0,0,0,1,1,2}; return v[k]; }
    static constexpr __host__ __device__ int pb(int k){ const int v[6]={0,1,2,1,2,2}; return v[k]; }
    static constexpr __host__ __device__ int gc(int k){ const int v[6]={3,3,3,4,4,5}; return v[k]; }
    static constexpr __host__ __device__ int ge(int k){ const int v[6]={3,4,5,4,5,5}; return v[k]; }
};
template<> struct WCfg<2> {                      // cross pairs, part 1
    static constexpr int NCH = 5, NP = 5;
    static constexpr bool SUMM = false;
    static constexpr __host__ __device__ int ch(int i){ const int v[5]={0,1,3,4,5}; return v[i]; }
    static constexpr __host__ __device__ int pa(int k){ const int v[5]={0,0,0,1,1}; return v[k]; }
    static constexpr __host__ __device__ int pb(int k){ const int v[5]={2,3,4,2,3}; return v[k]; }
    static constexpr __host__ __device__ int gc(int k){ const int v[5]={0,0,0,1,1}; return v[k]; }
    static constexpr __host__ __device__ int ge(int k){ const int v[5]={3,4,5,3,4}; return v[k]; }
};
template<> struct WCfg<3> {                      // cross pairs, part 2 + mask sums
    static constexpr int NCH = 5, NP = 4;
    static constexpr bool SUMM = true;
    static constexpr __host__ __device__ int ch(int i){ const int v[5]={1,2,3,4,5}; return v[i]; }
    static constexpr __host__ __device__ int pa(int k){ const int v[4]={0,1,1,1}; return v[k]; }
    static constexpr __host__ __device__ int pb(int k){ const int v[4]={4,2,3,4}; return v[k]; }
    static constexpr __host__ __device__ int gc(int k){ const int v[4]={1,2,2,2}; return v[k]; }
    static constexpr __host__ __device__ int ge(int k){ const int v[4]={5,3,4,5}; return v[k]; }
};

template<int WID>
__device__ __forceinline__ void psd_w(
    const float2* __restrict__ sr2, const float2* __restrict__ si2,
    const float2* __restrict__ ms2, const float2* __restrict__ mn2,
    int lane, float* __restrict__ s_acc)
{
    using W = WCfg<WID>;
    float asr[W::NP], anr[W::NP], asi[W::NP], ani[W::NP];
    #pragma unroll
    for (int k = 0; k < W::NP; ++k) { asr[k]=0.f; anr[k]=0.f; asi[k]=0.f; ani[k]=0.f; }
    float sms = 0.f, smn = 0.f;

    for (int p = lane; p < P_; p += 32) {
        float2 xr[W::NCH], xi[W::NCH];
        #pragma unroll
        for (int i = 0; i < W::NCH; ++i) {
            xr[i] = sr2[W::ch(i)*P_ + p];
            xi[i] = si2[W::ch(i)*P_ + p];
        }
        const float2 m_s = ms2[p];
        const float2 m_n = mn2[p];
        if (W::SUMM) { sms += m_s.x + m_s.y; smn += m_n.x + m_n.y; }

        #pragma unroll
        for (int k = 0; k < W::NP; ++k) {
            const int a = W::pa(k), b = W::pb(k);
            float r0 = xr[a].x*xr[b].x + xi[a].x*xi[b].x;
            float r1 = xr[a].y*xr[b].y + xi[a].y*xi[b].y;
            asr[k] += m_s.x*r0 + m_s.y*r1;
            anr[k] += m_n.x*r0 + m_n.y*r1;
            if (W::gc(k) != W::ge(k)) {
                float i0 = xi[a].x*xr[b].x - xr[a].x*xi[b].x;
                float i1 = xi[a].y*xr[b].y - xr[a].y*xi[b].y;
                asi[k] += m_s.x*i0 + m_s.y*i1;
                ani[k] += m_n.x*i0 + m_n.y*i1;
            }
        }
    }

    #pragma unroll
    for (int off = 16; off > 0; off >>= 1) {
        #pragma unroll
        for (int k = 0; k < W::NP; ++k) {
            asr[k] += __shfl_down_sync(0xffffffffu, asr[k], off);
            anr[k] += __shfl_down_sync(0xffffffffu, anr[k], off);
            if (W::gc(k) != W::ge(k)) {
                asi[k] += __shfl_down_sync(0xffffffffu, asi[k], off);
                ani[k] += __shfl_down_sync(0xffffffffu, ani[k], off);
            }
        }
        if (W::SUMM) {
            sms += __shfl_down_sync(0xffffffffu, sms, off);
            smn += __shfl_down_sync(0xffffffffu, smn, off);
        }
    }
    if (lane == 0) {
        #pragma unroll
        for (int k = 0; k < W::NP; ++k) {
            const int c = W::gc(k), e = W::ge(k);
            const int kg = c*(11 - c)/2 + e;
            s_acc[kg]      = asr[k];
            s_acc[36 + kg] = anr[k];
            if (c != e) {
                const int kig = kg - (c + 1);
                s_acc[21 + kig] = asi[k];
                s_acc[57 + kig] = ani[k];
            }
        }
        if (W::SUMM) { s_acc[72] = sms; s_acc[73] = smn; }
    }
}

__global__ __launch_bounds__(THREADS, 8)
void mvdr_kernel(const float* __restrict__ spec_r,
                 const float* __restrict__ spec_i,
                 const float* __restrict__ mask_s,
                 const float* __restrict__ mask_n,
                 float* __restrict__ out, int out_mode)
{
    __shared__ float  s_acc[ACC_N];
    __shared__ float2 M[C_][2*C_];
    __shared__ float2 fac[C_];
    __shared__ float2 wc[C_];

    const int bf   = blockIdx.x;
    const int tid  = threadIdx.x;
    const int lane = tid & 31;
    const int wid  = tid >> 5;

    const float2* sr2 = (const float2*)(spec_r + (size_t)bf * (C_*T_));
    const float2* si2 = (const float2*)(spec_i + (size_t)bf * (C_*T_));
    const float2* ms2 = (const float2*)(mask_s + (size_t)bf * T_);
    const float2* mn2 = (const float2*)(mask_n + (size_t)bf * T_);

    // ---- Phase 1+2: channel-grouped PSD accumulation, warp-local reduce ----
    if      (wid == 0) psd_w<0>(sr2, si2, ms2, mn2, lane, s_acc);
    else if (wid == 1) psd_w<1>(sr2, si2, ms2, mn2, lane, s_acc);
    else if (wid == 2) psd_w<2>(sr2, si2, ms2, mn2, lane, s_acc);
    else               psd_w<3>(sr2, si2, ms2, mn2, lane, s_acc);
    __syncthreads();

    // ---- Phase 3: build [psd_n | psd_s], 72-thread Gaussian elimination ----
    if (tid < 72) {
        const int r  = tid / 12;
        const int j  = tid % 12;
        const bool isS = (j >= 6);
        const int c2 = isS ? (j - 6) : j;
        const int cc = (r < c2) ? r : c2;
        const int ee = (r < c2) ? c2 : r;
        const int k  = cc*(11 - cc)/2 + ee;
        const int ki = k - (cc + 1);

        const float norm = isS ? (1.0f/(s_acc[72] + PSD_EPS))
                               : (1.0f/(s_acc[73] + PSD_EPS));
        const int reBase = isS ? 0 : 36;
        const int imBase = isS ? 21 : 57;

        float re = s_acc[reBase + k] * norm;
        float im = (r == c2) ? 0.0f : s_acc[imBase + ki] * norm;
        if (r > c2) im = -im;

        if (!isS && r == c2) {
            float trn = (s_acc[36+0] + s_acc[36+6] + s_acc[36+11] +
                         s_acc[36+15] + s_acc[36+18] + s_acc[36+20]) *
                        (1.0f/(s_acc[73] + PSD_EPS));
            re += trn * DIAG_EPS + EPS_;
        }
        M[r][j] = make_float2(re, im);
    }
    __syncthreads();

    const int r = tid / 12;
    const int j = tid % 12;
    #pragma unroll
    for (int kk = 0; kk < C_ - 1; ++kk) {
        if (tid < 72 && j == kk && r > kk)
            fac[r] = cdiv(M[r][kk], M[kk][kk]);
        __syncthreads();
        if (tid < 72 && r > kk) {
            float2 f = fac[r];
            float2 p = M[kk][j];
            float2 v = M[r][j];
            v.x -= f.x*p.x - f.y*p.y;
            v.y -= f.x*p.y + f.y*p.x;
            M[r][j] = v;
        }
        __syncthreads();
    }

    if (tid < C_) {
        #pragma unroll
        for (int kk = C_ - 1; kk >= 0; --kk) {
            float2 acc = M[kk][6 + tid];
            #pragma unroll
            for (int i = C_ - 1; i >= 1; --i) {
                if (i > kk) {
                    float2 a = M[kk][i];
                    float2 w = M[i][6 + tid];
                    acc.x -= a.x*w.x - a.y*w.y;
                    acc.y -= a.x*w.y + a.y*w.x;
                }
            }
            M[kk][6 + tid] = cdiv(acc, M[kk][kk]);
        }
    }
    __syncthreads();

    if (tid == 0) {
        float2 tr = make_float2(0.f, 0.f);
        #pragma unroll
        for (int d = 0; d < C_; ++d) { tr.x += M[d][6+d].x; tr.y += M[d][6+d].y; }
        float2 denom = make_float2(tr.x + EPS_, tr.y);
        #pragma unroll
        for (int c = 0; c < C_; ++c) {
            float2 w = cdiv(M[c][6 + 0], denom);   // REF_CHANNEL = 0
            wc[c] = make_float2(w.x, -w.y);        // conj(w)
        }
    }
    __syncthreads();

    // ---- Phase 4: beamform, float2 re-read (L1/L2-resident), float4 stores ----
    float2 wreg[C_];
    #pragma unroll
    for (int c = 0; c < C_; ++c) wreg[c] = wc[c];

    if (out_mode == 0) {
        float4* o4 = (float4*)out + (size_t)bf * P_;
        for (int p = tid; p < P_; p += THREADS) {
            float ar0 = 0.f, ai0 = 0.f, ar1 = 0.f, ai1 = 0.f;
            #pragma unroll
            for (int c = 0; c < C_; ++c) {
                float2 xr = sr2[c*P_ + p];
                float2 xi = si2[c*P_ + p];
                ar0 += wreg[c].x*xr.x - wreg[c].y*xi.x;
                ai0 += wreg[c].x*xi.x + wreg[c].y*xr.x;
                ar1 += wreg[c].x*xr.y - wreg[c].y*xi.y;
                ai1 += wreg[c].x*xi.y + wreg[c].y*xr.y;
            }
            o4[p] = make_float4(ar0, ai0, ar1, ai1);
        }
    } else {
        float2* o2 = (float2*)(out + (size_t)bf * T_);
        for (int p = tid; p < P_; p += THREADS) {
            float ar0 = 0.f, ar1 = 0.f;
            #pragma unroll
            for (int c = 0; c < C_; ++c) {
                float2 xr = sr2[c*P_ + p];
                float2 xi = si2[c*P_ + p];
                ar0 += wreg[c].x*xr.x - wreg[c].y*xi.x;
                ar1 += wreg[c].x*xr.y - wreg[c].y*xi.y;
            }
            o2[p] = make_float2(ar0, ar1);
        }
    }
}

extern "C" void kernel_launch(void* const* d_in, const int* in_sizes, int n_in,
                              void* d_out, int out_size) {
    const long long SPEC_N = (long long)B_ * F_ * C_ * T_;   // 24,600,000
    const long long MASK_N = (long long)B_ * F_ * T_;        //  4,100,000

    const float* ptr[4] = {nullptr, nullptr, nullptr, nullptr};
    for (int i = 0; i < n_in; ++i) {
        long long sz = (long long)in_sizes[i];
        const float* p = (const float*)d_in[i];
        if (sz == SPEC_N) {
            if (!ptr[0]) ptr[0] = p; else if (!ptr[1]) ptr[1] = p;
        } else if (sz == MASK_N) {
            if (!ptr[2]) ptr[2] = p; else if (!ptr[3]) ptr[3] = p;
        }
    }
    for (int s = 0; s < 4; ++s) {
        if (!ptr[s]) {
            int i = (s < n_in) ? s : (n_in - 1);
            ptr[s] = (const float*)d_in[i];
        }
    }

    const int out_mode = ((long long)out_size >= 2 * MASK_N) ? 0 : 1;

    mvdr_kernel<<<B_ * F_, THREADS>>>(ptr[0], ptr[1], ptr[2], ptr[3],
                                      (float*)d_out, out_mode);
}